// round 16
// baseline (speedup 1.0000x reference)
#include <cuda_runtime.h>
#include <math.h>

#define SS  8192
#define IND 128
#define DD  64
#define NT  608            // 19 warps, each warp owns one position (all 8 batches)
#define WARPS (NT/32)
#define SROWP 132          // S row stride (floats): bank-shifts bp rows
#define X2ROW 260          // X2 row stride (floats)

#define W_FLOATS (2*IND*DD + 5*DD*DD + 6*DD)   // weights + g/b arrays = 37248
#define STAGE_PER_WARP 1040                    // X2 (4*260); S (4*132) overlaps
#define SMEM_FLOATS (W_FLOATS + WARPS*STAGE_PER_WARP)
#define SMEM_BYTES  (SMEM_FLOATS*4)            // 228,032 B (<= 232,448 max)

typedef unsigned long long ull;

// phi table: phiT[s][j*64+i] = cos(2*pi*s/(i*64+j+2)), 128 MiB static
__device__ float g_phiT[SS * DD * DD];

// ---- packed f32x2 helpers (sm_100) ----
__device__ __forceinline__ ull dup2(float a){ ull r; asm("mov.b64 %0, {%1,%1};":"=l"(r):"f"(a)); return r; }
__device__ __forceinline__ ull pk2(float x,float y){ ull r; asm("mov.b64 %0, {%1,%2};":"=l"(r):"f"(x),"f"(y)); return r; }
__device__ __forceinline__ float2 up2(ull v){ float2 f; asm("mov.b64 {%0,%1}, %2;":"=f"(f.x),"=f"(f.y):"l"(v)); return f; }
__device__ __forceinline__ void fma2(ull&d, ull a, ull b){ asm("fma.rn.f32x2 %0, %1, %2, %0;":"+l"(d):"l"(a),"l"(b)); }
__device__ __forceinline__ ull mul2(ull a, ull b){ ull r; asm("mul.rn.f32x2 %0, %1, %2;":"=l"(r):"l"(a),"l"(b)); return r; }
__device__ __forceinline__ ull add2(ull a, ull b){ ull r; asm("add.rn.f32x2 %0, %1, %2;":"=l"(r):"l"(a),"l"(b)); return r; }

// cos(2*pi*s/p) via exact integer mod (s,p integers < 2^14)
__device__ __forceinline__ float pcosf(float sf, float pf){
    float rp; asm("rcp.approx.f32 %0, %1;" : "=f"(rp) : "f"(pf));
    float q = rintf(sf * rp);
    float m = fmaf(q, -pf, sf);
    float v = m * rp;
    return __cosf(v * 6.28318530717958647692f);
}

// ---- kernel A: fill phi table (transposed [s][j*64+i]) ----
__global__ __launch_bounds__(256, 4)
void phi_fill(void){
    const int s = blockIdx.x;
    const float sf = (float)s;
    float* row = g_phiT + (size_t)s * (DD*DD);
#pragma unroll
    for (int u = 0; u < (DD*DD)/256; u++){
        int idx = u*256 + threadIdx.x;     // idx = j*64 + i
        int i = idx & 63, j = idx >> 6;
        row[idx] = pcosf(sf, (float)(i*DD + j + 2));
    }
}

// ---- LayerNorm in (i x b)-split layout ----
// y0[k] = {val[i_k, 2bp], val[i_k+1, 2bp]}, y1 = batch 2bp+1.
// i_k = ig*4+2k (k<2) or 32+ig*4+2(k-2). Sum over i = intra-lane + xor{1,2,4}.
__device__ __forceinline__ void ln_v3(ull y0[4], ull y1[4],
                                      const float* sg, const float* sbeta, int ig4){
    ull t0 = add2(add2(y0[0],y0[1]), add2(y0[2],y0[3]));
    ull t1 = add2(add2(y1[0],y1[1]), add2(y1[2],y1[3]));
    float2 f0 = up2(t0), f1 = up2(t1);
    float s0 = f0.x + f0.y, s1 = f1.x + f1.y;
#pragma unroll
    for (int o=1;o<8;o<<=1){
        s0 += __shfl_xor_sync(0xffffffffu, s0, o);
        s1 += __shfl_xor_sync(0xffffffffu, s1, o);
    }
    ull m0 = dup2(s0 * -0.015625f), m1 = dup2(s1 * -0.015625f);
#pragma unroll
    for (int k=0;k<4;k++){ y0[k]=add2(y0[k],m0); y1[k]=add2(y1[k],m1); }
    ull q0 = mul2(y0[0],y0[0]); fma2(q0,y0[1],y0[1]); fma2(q0,y0[2],y0[2]); fma2(q0,y0[3],y0[3]);
    ull q1 = mul2(y1[0],y1[0]); fma2(q1,y1[1],y1[1]); fma2(q1,y1[2],y1[2]); fma2(q1,y1[3],y1[3]);
    f0 = up2(q0); f1 = up2(q1);
    float v0 = f0.x+f0.y, v1 = f1.x+f1.y;
#pragma unroll
    for (int o=1;o<8;o<<=1){
        v0 += __shfl_xor_sync(0xffffffffu, v0, o);
        v1 += __shfl_xor_sync(0xffffffffu, v1, o);
    }
    ull r0 = dup2(rsqrtf(fmaf(v0, 0.015625f, 1e-5f)));
    ull r1 = dup2(rsqrtf(fmaf(v1, 0.015625f, 1e-5f)));
    ulonglong2 Ga = *(const ulonglong2*)(sg + ig4);
    ulonglong2 Gb = *(const ulonglong2*)(sg + 32 + ig4);
    ulonglong2 Ba = *(const ulonglong2*)(sbeta + ig4);
    ulonglong2 Bb = *(const ulonglong2*)(sbeta + 32 + ig4);
    ull G[4]  = {Ga.x, Ga.y, Gb.x, Gb.y};
    ull Bt[4] = {Ba.x, Ba.y, Bb.x, Bb.y};
#pragma unroll
    for (int k=0;k<4;k++){
        ull u0 = mul2(y0[k], r0), u1 = mul2(y1[k], r1);
        y0[k] = Bt[k]; fma2(y0[k], u0, G[k]);
        y1[k] = Bt[k]; fma2(y1[k], u1, G[k]);
    }
}

// 64x64 matvec, (i x b)-split: per j: 2 LDS.128 weights + 1 LDS.64 act.
__device__ __forceinline__ void mm_v3(const float* __restrict__ Wt,
                                      const float* __restrict__ S,
                                      int ig4, int bp, ull y0[4], ull y1[4]){
    const float* act_p = S + bp*SROWP;
#pragma unroll 4
    for (int j=0;j<DD;j++){
        const float* wr = Wt + j*DD;
        ulonglong2 wa = *(const ulonglong2*)(wr + ig4);       // i-pairs k=0,1
        ulonglong2 wb = *(const ulonglong2*)(wr + 32 + ig4);  // i-pairs k=2,3
        ull act = *(const ull*)(act_p + 2*j);
        float2 a = up2(act);
        ull d0 = dup2(a.x), d1 = dup2(a.y);
        fma2(y0[0],wa.x,d0); fma2(y1[0],wa.x,d1);
        fma2(y0[1],wa.y,d0); fma2(y1[1],wa.y,d1);
        fma2(y0[2],wb.x,d0); fma2(y1[2],wb.x,d1);
        fma2(y0[3],wb.y,d0); fma2(y1[3],wb.y,d1);
    }
}

// Phase matvec: weights = P[j][i-pair] * phi[s][j][i-pair] (direct ull mul).
__device__ __forceinline__ void nmv_v3(const float* __restrict__ Pt,
                                       const float* __restrict__ phis,
                                       const float* __restrict__ S,
                                       int ig4, int bp, ull y0[4], ull y1[4]){
    const float* act_p = S + bp*SROWP;
#pragma unroll 4
    for (int j=0;j<DD;j++){
        const float* pr = Pt + j*DD;
        const float* fr = phis + j*DD;
        ulonglong2 wa = *(const ulonglong2*)(pr + ig4);
        ulonglong2 wb = *(const ulonglong2*)(pr + 32 + ig4);
        ulonglong2 fa = *(const ulonglong2*)(fr + ig4);
        ulonglong2 fb = *(const ulonglong2*)(fr + 32 + ig4);
        wa.x = mul2(wa.x, fa.x);  wa.y = mul2(wa.y, fa.y);
        wb.x = mul2(wb.x, fb.x);  wb.y = mul2(wb.y, fb.y);
        ull act = *(const ull*)(act_p + 2*j);
        float2 a = up2(act);
        ull d0 = dup2(a.x), d1 = dup2(a.y);
        fma2(y0[0],wa.x,d0); fma2(y1[0],wa.x,d1);
        fma2(y0[1],wa.y,d0); fma2(y1[1],wa.y,d1);
        fma2(y0[2],wb.x,d0); fma2(y1[2],wb.x,d1);
        fma2(y0[3],wb.y,d0); fma2(y1[3],wb.y,d1);
    }
}

// store acc-layout values into S[bp][j] = {val[j,2bp], val[j,2bp+1]}
__device__ __forceinline__ void store_s(float* S, int ig4, int bp,
                                        const ull y0[4], const ull y1[4]){
    float* base = S + bp*SROWP;
#pragma unroll
    for (int h=0; h<2; h++){
        int io = h ? (32 + ig4) : ig4;
        float2 e0 = up2(y0[2*h]),   o0 = up2(y1[2*h]);
        float2 e1 = up2(y0[2*h+1]), o1 = up2(y1[2*h+1]);
        ulonglong2 t0; t0.x = pk2(e0.x, o0.x); t0.y = pk2(e0.y, o0.y);
        ulonglong2 t1; t1.x = pk2(e1.x, o1.x); t1.y = pk2(e1.y, o1.y);
        *(ulonglong2*)(base + 2*io)     = t0;
        *(ulonglong2*)(base + 2*io + 4) = t1;
    }
}

__global__ __launch_bounds__(NT, 1)
void hier_fused9(const float* __restrict__ seq,
                 const float* __restrict__ M1, const float* __restrict__ P1,
                 const float* __restrict__ g1, const float* __restrict__ b1,
                 const float* __restrict__ Wr1,
                 const float* __restrict__ M2, const float* __restrict__ P2,
                 const float* __restrict__ g2, const float* __restrict__ b2,
                 const float* __restrict__ M3, const float* __restrict__ P3,
                 const float* __restrict__ g3, const float* __restrict__ b3,
                 float* __restrict__ out)
{
    extern __shared__ float sm[];
    float* sM1T = sm;                    // [j][i] 128x64
    float* sWrT = sM1T + IND*DD;         // 128x64
    float* sM2T = sWrT + IND*DD;         // 64x64 each
    float* sM3T = sM2T + DD*DD;
    float* sP1T = sM3T + DD*DD;
    float* sP2T = sP1T + DD*DD;
    float* sP3T = sP2T + DD*DD;
    float* sG1  = sP3T + DD*DD;          // 6 x 64 g/b arrays
    float* sB1  = sG1 + DD;
    float* sG2  = sB1 + DD;
    float* sB2  = sG2 + DD;
    float* sG3  = sB2 + DD;
    float* sB3  = sG3 + DD;
    float* stage = sB3 + DD;

    const int tid = threadIdx.x;
    const int wid = tid >> 5;
    const int l   = tid & 31;
    const int bp  = l >> 3;          // batch pair 0..3
    const int ig  = l & 7;           // i-group 0..7
    const int ig4 = ig * 4;

    float* X2 = stage + wid*STAGE_PER_WARP;  // [bp][j] ull input, stride X2ROW
    float* S  = X2;                          // [bp][j] ull staging, stride SROWP (overlap OK)

    // ---- preload weights transposed into SMEM ----
    for (int idx = tid; idx < IND*DD; idx += NT){
        int i = idx >> 7, j = idx & 127;
        sM1T[j*DD + i] = M1[idx];
        sWrT[j*DD + i] = Wr1[idx];
    }
    for (int idx = tid; idx < DD*DD; idx += NT){
        int i = idx >> 6, j = idx & 63;
        sM2T[j*DD + i] = M2[idx];
        sM3T[j*DD + i] = M3[idx];
        sP1T[j*DD + i] = P1[idx];
        sP2T[j*DD + i] = P2[idx];
        sP3T[j*DD + i] = P3[idx];
    }
    if (tid < DD){
        sG1[tid] = g1[tid];  sB1[tid] = b1[tid];
        sG2[tid] = g2[tid];  sB2[tid] = b2[tid];
        sG3[tid] = g3[tid];  sB3[tid] = b3[tid];
    }
    __syncthreads();

    const int stride = gridDim.x * WARPS;
    const int bq = l & 3, jb = l >> 2;   // input repack mapping

    for (int s = blockIdx.x*WARPS + wid; s < SS; s += stride){
        const float* phis = g_phiT + (size_t)s * (DD*DD);

        // ---- prefetch phi row toward L2 (cheap) ----
#pragma unroll
        for (int u = 0; u < 4; u++)
            asm volatile("prefetch.global.L2 [%0];"
                         :: "l"(phis + (u*32 + l) * 32) : "memory");

        // ---- load input, repack to [bp][j] batch-pair ulls in registers ----
#pragma unroll
        for (int r=0;r<4;r++){
            int j = jb*4 + r*32;
            float4 va = *(const float4*)(seq + ((size_t)(2*bq  )*SS + s)*IND + j);
            float4 vb = *(const float4*)(seq + ((size_t)(2*bq+1)*SS + s)*IND + j);
            ulonglong2 t0; t0.x = pk2(va.x, vb.x); t0.y = pk2(va.y, vb.y);
            ulonglong2 t1; t1.x = pk2(va.z, vb.z); t1.y = pk2(va.w, vb.w);
            *(ulonglong2*)(X2 + bq*X2ROW + 2*j)     = t0;
            *(ulonglong2*)(X2 + bq*X2ROW + 2*j + 4) = t1;
        }
        __syncwarp();

        // ====== layer 1: xt = x@M1T, rr = x@WrT ((i x b)-split) ======
        ull xt0[4], xt1[4], rr0[4], rr1[4];
#pragma unroll
        for (int k=0;k<4;k++){ xt0[k]=0ull; xt1[k]=0ull; rr0[k]=0ull; rr1[k]=0ull; }
        {
            const float* act_p = X2 + bp*X2ROW;
#pragma unroll 2
            for (int j=0;j<IND;j++){
                const float* mr = sM1T + j*DD;
                const float* wr = sWrT + j*DD;
                ulonglong2 ma = *(const ulonglong2*)(mr + ig4);
                ulonglong2 mb = *(const ulonglong2*)(mr + 32 + ig4);
                ulonglong2 wa = *(const ulonglong2*)(wr + ig4);
                ulonglong2 wb = *(const ulonglong2*)(wr + 32 + ig4);
                ull act = *(const ull*)(act_p + 2*j);
                float2 a = up2(act);
                ull d0 = dup2(a.x), d1 = dup2(a.y);
                fma2(xt0[0],ma.x,d0); fma2(xt1[0],ma.x,d1);
                fma2(xt0[1],ma.y,d0); fma2(xt1[1],ma.y,d1);
                fma2(xt0[2],mb.x,d0); fma2(xt1[2],mb.x,d1);
                fma2(xt0[3],mb.y,d0); fma2(xt1[3],mb.y,d1);
                fma2(rr0[0],wa.x,d0); fma2(rr1[0],wa.x,d1);
                fma2(rr0[1],wa.y,d0); fma2(rr1[1],wa.y,d1);
                fma2(rr0[2],wb.x,d0); fma2(rr1[2],wb.x,d1);
                fma2(rr0[3],wb.y,d0); fma2(rr1[3],wb.y,d1);
            }
        }
        ln_v3(xt0, xt1, sG1, sB1, ig4);
        __syncwarp();                 // X2 reads complete before S overwrite
        store_s(S, ig4, bp, xt0, xt1);
        __syncwarp();
        ull z0[4], z1[4];
#pragma unroll
        for (int k=0;k<4;k++){ z0[k]=0ull; z1[k]=0ull; }
        nmv_v3(sP1T, phis, S, ig4, bp, z0, z1);
#pragma unroll
        for (int k=0;k<4;k++){ z0[k]=add2(z0[k],rr0[k]); z1[k]=add2(z1[k],rr1[k]); }

        // ====== layer 2 ======
        __syncwarp();
        store_s(S, ig4, bp, z0, z1);
        __syncwarp();
#pragma unroll
        for (int k=0;k<4;k++){ xt0[k]=0ull; xt1[k]=0ull; }
        mm_v3(sM2T, S, ig4, bp, xt0, xt1);
        ln_v3(xt0, xt1, sG2, sB2, ig4);
        __syncwarp();
        store_s(S, ig4, bp, xt0, xt1);
        __syncwarp();
        ull nn0[4], nn1[4];
#pragma unroll
        for (int k=0;k<4;k++){ nn0[k]=0ull; nn1[k]=0ull; }
        nmv_v3(sP2T, phis, S, ig4, bp, nn0, nn1);
#pragma unroll
        for (int k=0;k<4;k++){ z0[k]=add2(nn0[k],z0[k]); z1[k]=add2(nn1[k],z1[k]); }

        // ====== layer 3 ======
        __syncwarp();
        store_s(S, ig4, bp, z0, z1);
        __syncwarp();
#pragma unroll
        for (int k=0;k<4;k++){ xt0[k]=0ull; xt1[k]=0ull; }
        mm_v3(sM3T, S, ig4, bp, xt0, xt1);
        ln_v3(xt0, xt1, sG3, sB3, ig4);
        __syncwarp();
        store_s(S, ig4, bp, xt0, xt1);
        __syncwarp();
#pragma unroll
        for (int k=0;k<4;k++){ nn0[k]=0ull; nn1[k]=0ull; }
        nmv_v3(sP3T, phis, S, ig4, bp, nn0, nn1);
#pragma unroll
        for (int k=0;k<4;k++){ z0[k]=add2(nn0[k],z0[k]); z1[k]=add2(nn1[k],z1[k]); }

        // ---- store: z0[k]/z1[k] are already i-pair ulls per batch ----
#pragma unroll
        for (int k=0;k<4;k++){
            int i = (k < 2) ? (ig4 + 2*k) : (32 + ig4 + 2*(k-2));
            *(ull*)(out + ((size_t)(2*bp  )*SS + s)*DD + i) = z0[k];
            *(ull*)(out + ((size_t)(2*bp+1)*SS + s)*DD + i) = z1[k];
        }
    }
}

extern "C" void kernel_launch(void* const* d_in, const int* in_sizes, int n_in,
                              void* d_out, int out_size) {
    const float* seq = (const float*)d_in[0];
    const float* M1  = (const float*)d_in[1];
    const float* P1  = (const float*)d_in[2];
    const float* g1  = (const float*)d_in[3];
    const float* b1  = (const float*)d_in[4];
    const float* Wr1 = (const float*)d_in[5];
    const float* M2  = (const float*)d_in[6];
    const float* P2  = (const float*)d_in[7];
    const float* g2  = (const float*)d_in[8];
    const float* b2  = (const float*)d_in[9];
    const float* M3  = (const float*)d_in[10];
    const float* P3  = (const float*)d_in[11];
    const float* g3  = (const float*)d_in[12];
    const float* b3  = (const float*)d_in[13];
    float* out = (float*)d_out;

    cudaFuncSetAttribute(hier_fused9,
                         cudaFuncAttributeMaxDynamicSharedMemorySize, SMEM_BYTES);

    int dev = 0, sms = 148;
    if (cudaGetDevice(&dev) == cudaSuccess) {
        int v = 0;
        if (cudaDeviceGetAttribute(&v, cudaDevAttrMultiProcessorCount, dev) == cudaSuccess
            && v > 0) sms = v;
    }

    phi_fill<<<SS, 256>>>();
    hier_fused9<<<sms, NT, SMEM_BYTES>>>(seq, M1, P1, g1, b1, Wr1,
                                         M2, P2, g2, b2, M3, P3, g3, b3, out);
}

// round 17
// speedup vs baseline: 1.0069x; 1.0069x over previous
#include <cuda_runtime.h>
#include <math.h>

#define SS  8192
#define IND 128
#define DD  64
#define NT  608            // 19 warps, each warp owns one position (all 8 batches)
#define WARPS (NT/32)
#define SROWP 132          // S row stride (floats): bank-shifts bp rows
#define X2ROW 260          // X2 row stride (floats)

#define W_FLOATS (2*IND*DD + 5*DD*DD + 6*DD)   // weights + g/b arrays = 37248
#define STAGE_PER_WARP 1040                    // X2 (4*260); S (4*132) overlaps
#define SMEM_FLOATS (W_FLOATS + WARPS*STAGE_PER_WARP)
#define SMEM_BYTES  (SMEM_FLOATS*4)            // 228,032 B (<= 232,448 max)

typedef unsigned long long ull;

// phi table: phiT[s][j*64+i] = cos(2*pi*s/(i*64+j+2)), 128 MiB static
__device__ float g_phiT[SS * DD * DD];

// ---- packed f32x2 helpers (sm_100) ----
__device__ __forceinline__ ull dup2(float a){ ull r; asm("mov.b64 %0, {%1,%1};":"=l"(r):"f"(a)); return r; }
__device__ __forceinline__ ull pk2(float x,float y){ ull r; asm("mov.b64 %0, {%1,%2};":"=l"(r):"f"(x),"f"(y)); return r; }
__device__ __forceinline__ float2 up2(ull v){ float2 f; asm("mov.b64 {%0,%1}, %2;":"=f"(f.x),"=f"(f.y):"l"(v)); return f; }
__device__ __forceinline__ void fma2(ull&d, ull a, ull b){ asm("fma.rn.f32x2 %0, %1, %2, %0;":"+l"(d):"l"(a),"l"(b)); }
__device__ __forceinline__ ull mul2(ull a, ull b){ ull r; asm("mul.rn.f32x2 %0, %1, %2;":"=l"(r):"l"(a),"l"(b)); return r; }
__device__ __forceinline__ ull add2(ull a, ull b){ ull r; asm("add.rn.f32x2 %0, %1, %2;":"=l"(r):"l"(a),"l"(b)); return r; }

// cos(2*pi*s/p) via exact integer mod (s,p integers < 2^14)
__device__ __forceinline__ float pcosf(float sf, float pf){
    float rp; asm("rcp.approx.f32 %0, %1;" : "=f"(rp) : "f"(pf));
    float q = rintf(sf * rp);
    float m = fmaf(q, -pf, sf);
    float v = m * rp;
    return __cosf(v * 6.28318530717958647692f);
}

// ---- kernel A: fill phi table (transposed [s][j*64+i]) ----
__global__ __launch_bounds__(256, 4)
void phi_fill(void){
    const int s = blockIdx.x;
    const float sf = (float)s;
    float* row = g_phiT + (size_t)s * (DD*DD);
#pragma unroll
    for (int u = 0; u < (DD*DD)/256; u++){
        int idx = u*256 + threadIdx.x;     // idx = j*64 + i
        int i = idx & 63, j = idx >> 6;
        row[idx] = pcosf(sf, (float)(i*DD + j + 2));
    }
}

// ---- LayerNorm in (i x b)-split layout ----
// y0[k] = {val[i_k, 2bp], val[i_k+1, 2bp]}, y1 = batch 2bp+1.
// i_k = ig*4+2k (k<2) or 32+ig*4+2(k-2). Sum over i = intra-lane + xor{1,2,4}.
__device__ __forceinline__ void ln_v3(ull y0[4], ull y1[4],
                                      const float* sg, const float* sbeta, int ig4){
    ull t0 = add2(add2(y0[0],y0[1]), add2(y0[2],y0[3]));
    ull t1 = add2(add2(y1[0],y1[1]), add2(y1[2],y1[3]));
    float2 f0 = up2(t0), f1 = up2(t1);
    float s0 = f0.x + f0.y, s1 = f1.x + f1.y;
#pragma unroll
    for (int o=1;o<8;o<<=1){
        s0 += __shfl_xor_sync(0xffffffffu, s0, o);
        s1 += __shfl_xor_sync(0xffffffffu, s1, o);
    }
    ull m0 = dup2(s0 * -0.015625f), m1 = dup2(s1 * -0.015625f);
#pragma unroll
    for (int k=0;k<4;k++){ y0[k]=add2(y0[k],m0); y1[k]=add2(y1[k],m1); }
    ull q0 = mul2(y0[0],y0[0]); fma2(q0,y0[1],y0[1]); fma2(q0,y0[2],y0[2]); fma2(q0,y0[3],y0[3]);
    ull q1 = mul2(y1[0],y1[0]); fma2(q1,y1[1],y1[1]); fma2(q1,y1[2],y1[2]); fma2(q1,y1[3],y1[3]);
    f0 = up2(q0); f1 = up2(q1);
    float v0 = f0.x+f0.y, v1 = f1.x+f1.y;
#pragma unroll
    for (int o=1;o<8;o<<=1){
        v0 += __shfl_xor_sync(0xffffffffu, v0, o);
        v1 += __shfl_xor_sync(0xffffffffu, v1, o);
    }
    ull r0 = dup2(rsqrtf(fmaf(v0, 0.015625f, 1e-5f)));
    ull r1 = dup2(rsqrtf(fmaf(v1, 0.015625f, 1e-5f)));
    ulonglong2 Ga = *(const ulonglong2*)(sg + ig4);
    ulonglong2 Gb = *(const ulonglong2*)(sg + 32 + ig4);
    ulonglong2 Ba = *(const ulonglong2*)(sbeta + ig4);
    ulonglong2 Bb = *(const ulonglong2*)(sbeta + 32 + ig4);
    ull G[4]  = {Ga.x, Ga.y, Gb.x, Gb.y};
    ull Bt[4] = {Ba.x, Ba.y, Bb.x, Bb.y};
#pragma unroll
    for (int k=0;k<4;k++){
        ull u0 = mul2(y0[k], r0), u1 = mul2(y1[k], r1);
        y0[k] = Bt[k]; fma2(y0[k], u0, G[k]);
        y1[k] = Bt[k]; fma2(y1[k], u1, G[k]);
    }
}

// 64x64 matvec, (i x b)-split: per j: 2 LDS.128 weights + 1 LDS.64 act.
__device__ __forceinline__ void mm_v3(const float* __restrict__ Wt,
                                      const float* __restrict__ S,
                                      int ig4, int bp, ull y0[4], ull y1[4]){
    const float* act_p = S + bp*SROWP;
#pragma unroll 4
    for (int j=0;j<DD;j++){
        const float* wr = Wt + j*DD;
        ulonglong2 wa = *(const ulonglong2*)(wr + ig4);       // i-pairs k=0,1
        ulonglong2 wb = *(const ulonglong2*)(wr + 32 + ig4);  // i-pairs k=2,3
        ull act = *(const ull*)(act_p + 2*j);
        float2 a = up2(act);
        ull d0 = dup2(a.x), d1 = dup2(a.y);
        fma2(y0[0],wa.x,d0); fma2(y1[0],wa.x,d1);
        fma2(y0[1],wa.y,d0); fma2(y1[1],wa.y,d1);
        fma2(y0[2],wb.x,d0); fma2(y1[2],wb.x,d1);
        fma2(y0[3],wb.y,d0); fma2(y1[3],wb.y,d1);
    }
}

// Phase matvec: weights = P[j][i-pair] * phi[s][j][i-pair] (direct ull mul).
__device__ __forceinline__ void nmv_v3(const float* __restrict__ Pt,
                                       const float* __restrict__ phis,
                                       const float* __restrict__ S,
                                       int ig4, int bp, ull y0[4], ull y1[4]){
    const float* act_p = S + bp*SROWP;
#pragma unroll 4
    for (int j=0;j<DD;j++){
        const float* pr = Pt + j*DD;
        const float* fr = phis + j*DD;
        ulonglong2 wa = *(const ulonglong2*)(pr + ig4);
        ulonglong2 wb = *(const ulonglong2*)(pr + 32 + ig4);
        ulonglong2 fa = *(const ulonglong2*)(fr + ig4);
        ulonglong2 fb = *(const ulonglong2*)(fr + 32 + ig4);
        wa.x = mul2(wa.x, fa.x);  wa.y = mul2(wa.y, fa.y);
        wb.x = mul2(wb.x, fb.x);  wb.y = mul2(wb.y, fb.y);
        ull act = *(const ull*)(act_p + 2*j);
        float2 a = up2(act);
        ull d0 = dup2(a.x), d1 = dup2(a.y);
        fma2(y0[0],wa.x,d0); fma2(y1[0],wa.x,d1);
        fma2(y0[1],wa.y,d0); fma2(y1[1],wa.y,d1);
        fma2(y0[2],wb.x,d0); fma2(y1[2],wb.x,d1);
        fma2(y0[3],wb.y,d0); fma2(y1[3],wb.y,d1);
    }
}

// store acc-layout values into S[bp][j] = {val[j,2bp], val[j,2bp+1]}
__device__ __forceinline__ void store_s(float* S, int ig4, int bp,
                                        const ull y0[4], const ull y1[4]){
    float* base = S + bp*SROWP;
#pragma unroll
    for (int h=0; h<2; h++){
        int io = h ? (32 + ig4) : ig4;
        float2 e0 = up2(y0[2*h]),   o0 = up2(y1[2*h]);
        float2 e1 = up2(y0[2*h+1]), o1 = up2(y1[2*h+1]);
        ulonglong2 t0; t0.x = pk2(e0.x, o0.x); t0.y = pk2(e0.y, o0.y);
        ulonglong2 t1; t1.x = pk2(e1.x, o1.x); t1.y = pk2(e1.y, o1.y);
        *(ulonglong2*)(base + 2*io)     = t0;
        *(ulonglong2*)(base + 2*io + 4) = t1;
    }
}

__global__ __launch_bounds__(NT, 1)
void hier_fused9(const float* __restrict__ seq,
                 const float* __restrict__ M1, const float* __restrict__ P1,
                 const float* __restrict__ g1, const float* __restrict__ b1,
                 const float* __restrict__ Wr1,
                 const float* __restrict__ M2, const float* __restrict__ P2,
                 const float* __restrict__ g2, const float* __restrict__ b2,
                 const float* __restrict__ M3, const float* __restrict__ P3,
                 const float* __restrict__ g3, const float* __restrict__ b3,
                 float* __restrict__ out)
{
    extern __shared__ float sm[];
    float* sM1T = sm;                    // [j][i] 128x64
    float* sWrT = sM1T + IND*DD;         // 128x64
    float* sM2T = sWrT + IND*DD;         // 64x64 each
    float* sM3T = sM2T + DD*DD;
    float* sP1T = sM3T + DD*DD;
    float* sP2T = sP1T + DD*DD;
    float* sP3T = sP2T + DD*DD;
    float* sG1  = sP3T + DD*DD;          // 6 x 64 g/b arrays
    float* sB1  = sG1 + DD;
    float* sG2  = sB1 + DD;
    float* sB2  = sG2 + DD;
    float* sG3  = sB2 + DD;
    float* sB3  = sG3 + DD;
    float* stage = sB3 + DD;

    const int tid = threadIdx.x;
    const int wid = tid >> 5;
    const int l   = tid & 31;
    const int bp  = l >> 3;          // batch pair 0..3
    const int ig  = l & 7;           // i-group 0..7
    const int ig4 = ig * 4;

    float* X2 = stage + wid*STAGE_PER_WARP;  // [bp][j] ull input, stride X2ROW
    float* S  = X2;                          // [bp][j] ull staging, stride SROWP (overlap OK)

    // ---- preload weights transposed into SMEM ----
    for (int idx = tid; idx < IND*DD; idx += NT){
        int i = idx >> 7, j = idx & 127;
        sM1T[j*DD + i] = M1[idx];
        sWrT[j*DD + i] = Wr1[idx];
    }
    for (int idx = tid; idx < DD*DD; idx += NT){
        int i = idx >> 6, j = idx & 63;
        sM2T[j*DD + i] = M2[idx];
        sM3T[j*DD + i] = M3[idx];
        sP1T[j*DD + i] = P1[idx];
        sP2T[j*DD + i] = P2[idx];
        sP3T[j*DD + i] = P3[idx];
    }
    if (tid < DD){
        sG1[tid] = g1[tid];  sB1[tid] = b1[tid];
        sG2[tid] = g2[tid];  sB2[tid] = b2[tid];
        sG3[tid] = g3[tid];  sB3[tid] = b3[tid];
    }
    __syncthreads();

    const int stride = gridDim.x * WARPS;
    const int bq = l & 3, jb = l >> 2;   // input repack mapping

    for (int s = blockIdx.x*WARPS + wid; s < SS; s += stride){
        const float* phis = g_phiT + (size_t)s * (DD*DD);

        // ---- prefetch phi row toward L2 (cheap) ----
#pragma unroll
        for (int u = 0; u < 4; u++)
            asm volatile("prefetch.global.L2 [%0];"
                         :: "l"(phis + (u*32 + l) * 32) : "memory");

        // ---- load input, repack to [bp][j] batch-pair ulls in registers ----
#pragma unroll
        for (int r=0;r<4;r++){
            int j = jb*4 + r*32;
            float4 va = *(const float4*)(seq + ((size_t)(2*bq  )*SS + s)*IND + j);
            float4 vb = *(const float4*)(seq + ((size_t)(2*bq+1)*SS + s)*IND + j);
            ulonglong2 t0; t0.x = pk2(va.x, vb.x); t0.y = pk2(va.y, vb.y);
            ulonglong2 t1; t1.x = pk2(va.z, vb.z); t1.y = pk2(va.w, vb.w);
            *(ulonglong2*)(X2 + bq*X2ROW + 2*j)     = t0;
            *(ulonglong2*)(X2 + bq*X2ROW + 2*j + 4) = t1;
        }
        __syncwarp();

        // ====== layer 1: xt = x@M1T, rr = x@WrT ((i x b)-split) ======
        ull xt0[4], xt1[4], rr0[4], rr1[4];
#pragma unroll
        for (int k=0;k<4;k++){ xt0[k]=0ull; xt1[k]=0ull; rr0[k]=0ull; rr1[k]=0ull; }
        {
            const float* act_p = X2 + bp*X2ROW;
#pragma unroll 2
            for (int j=0;j<IND;j++){
                const float* mr = sM1T + j*DD;
                const float* wr = sWrT + j*DD;
                ulonglong2 ma = *(const ulonglong2*)(mr + ig4);
                ulonglong2 mb = *(const ulonglong2*)(mr + 32 + ig4);
                ulonglong2 wa = *(const ulonglong2*)(wr + ig4);
                ulonglong2 wb = *(const ulonglong2*)(wr + 32 + ig4);
                ull act = *(const ull*)(act_p + 2*j);
                float2 a = up2(act);
                ull d0 = dup2(a.x), d1 = dup2(a.y);
                fma2(xt0[0],ma.x,d0); fma2(xt1[0],ma.x,d1);
                fma2(xt0[1],ma.y,d0); fma2(xt1[1],ma.y,d1);
                fma2(xt0[2],mb.x,d0); fma2(xt1[2],mb.x,d1);
                fma2(xt0[3],mb.y,d0); fma2(xt1[3],mb.y,d1);
                fma2(rr0[0],wa.x,d0); fma2(rr1[0],wa.x,d1);
                fma2(rr0[1],wa.y,d0); fma2(rr1[1],wa.y,d1);
                fma2(rr0[2],wb.x,d0); fma2(rr1[2],wb.x,d1);
                fma2(rr0[3],wb.y,d0); fma2(rr1[3],wb.y,d1);
            }
        }
        ln_v3(xt0, xt1, sG1, sB1, ig4);
        __syncwarp();                 // X2 reads complete before S overwrite
        store_s(S, ig4, bp, xt0, xt1);
        __syncwarp();
        ull z0[4], z1[4];
#pragma unroll
        for (int k=0;k<4;k++){ z0[k]=0ull; z1[k]=0ull; }
        nmv_v3(sP1T, phis, S, ig4, bp, z0, z1);
#pragma unroll
        for (int k=0;k<4;k++){ z0[k]=add2(z0[k],rr0[k]); z1[k]=add2(z1[k],rr1[k]); }

        // ====== layer 2 ======
        __syncwarp();
        store_s(S, ig4, bp, z0, z1);
        __syncwarp();
#pragma unroll
        for (int k=0;k<4;k++){ xt0[k]=0ull; xt1[k]=0ull; }
        mm_v3(sM2T, S, ig4, bp, xt0, xt1);
        ln_v3(xt0, xt1, sG2, sB2, ig4);
        __syncwarp();
        store_s(S, ig4, bp, xt0, xt1);
        __syncwarp();
        ull nn0[4], nn1[4];
#pragma unroll
        for (int k=0;k<4;k++){ nn0[k]=0ull; nn1[k]=0ull; }
        nmv_v3(sP2T, phis, S, ig4, bp, nn0, nn1);
#pragma unroll
        for (int k=0;k<4;k++){ z0[k]=add2(nn0[k],z0[k]); z1[k]=add2(nn1[k],z1[k]); }

        // ====== layer 3 ======
        __syncwarp();
        store_s(S, ig4, bp, z0, z1);
        __syncwarp();
#pragma unroll
        for (int k=0;k<4;k++){ xt0[k]=0ull; xt1[k]=0ull; }
        mm_v3(sM3T, S, ig4, bp, xt0, xt1);
        ln_v3(xt0, xt1, sG3, sB3, ig4);
        __syncwarp();
        store_s(S, ig4, bp, xt0, xt1);
        __syncwarp();
#pragma unroll
        for (int k=0;k<4;k++){ nn0[k]=0ull; nn1[k]=0ull; }
        nmv_v3(sP3T, phis, S, ig4, bp, nn0, nn1);
#pragma unroll
        for (int k=0;k<4;k++){ z0[k]=add2(nn0[k],z0[k]); z1[k]=add2(nn1[k],z1[k]); }

        // ---- store: z0[k]/z1[k] are already i-pair ulls per batch ----
#pragma unroll
        for (int k=0;k<4;k++){
            int i = (k < 2) ? (ig4 + 2*k) : (32 + ig4 + 2*(k-2));
            *(ull*)(out + ((size_t)(2*bp  )*SS + s)*DD + i) = z0[k];
            *(ull*)(out + ((size_t)(2*bp+1)*SS + s)*DD + i) = z1[k];
        }
    }
}

extern "C" void kernel_launch(void* const* d_in, const int* in_sizes, int n_in,
                              void* d_out, int out_size) {
    const float* seq = (const float*)d_in[0];
    const float* M1  = (const float*)d_in[1];
    const float* P1  = (const float*)d_in[2];
    const float* g1  = (const float*)d_in[3];
    const float* b1  = (const float*)d_in[4];
    const float* Wr1 = (const float*)d_in[5];
    const float* M2  = (const float*)d_in[6];
    const float* P2  = (const float*)d_in[7];
    const float* g2  = (const float*)d_in[8];
    const float* b2  = (const float*)d_in[9];
    const float* M3  = (const float*)d_in[10];
    const float* P3  = (const float*)d_in[11];
    const float* g3  = (const float*)d_in[12];
    const float* b3  = (const float*)d_in[13];
    float* out = (float*)d_out;

    cudaFuncSetAttribute(hier_fused9,
                         cudaFuncAttributeMaxDynamicSharedMemorySize, SMEM_BYTES);

    int dev = 0, sms = 148;
    if (cudaGetDevice(&dev) == cudaSuccess) {
        int v = 0;
        if (cudaDeviceGetAttribute(&v, cudaDevAttrMultiProcessorCount, dev) == cudaSuccess
            && v > 0) sms = v;
    }

    phi_fill<<<SS, 256>>>();
    hier_fused9<<<sms, NT, SMEM_BYTES>>>(seq, M1, P1, g1, b1, Wr1,
                                         M2, P2, g2, b2, M3, P3, g3, b3, out);
}